// round 2
// baseline (speedup 1.0000x reference)
#include <cuda_runtime.h>
#include <cstdint>
#include <cstddef>

#define NN 100000
#define EE 1000000
#define DD 128
#define HH 8
#define SCALE_ATT 0.25f   // 1/sqrt(16)

// ---------------- scratch (static device globals; no allocation allowed) ----
__device__ float    g_q[NN * DD];
__device__ float    g_k[NN * DD];
__device__ float    g_v[NN * DD];
__device__ float    g_skip[NN * DD];
__device__ float    g_h[NN * DD];
__device__ float    g_num[NN * DD];
__device__ float    g_score[(size_t)EE * HH];
__device__ unsigned g_m[NN * HH];     // order-encoded float max
__device__ float    g_s[NN * HH];

// order-preserving float<->uint encoding for atomicMax over signed floats
__device__ __forceinline__ unsigned enc_f(float f) {
    unsigned u = __float_as_uint(f);
    return (u & 0x80000000u) ? ~u : (u | 0x80000000u);
}
__device__ __forceinline__ float dec_f(unsigned e) {
    return (e & 0x80000000u) ? __uint_as_float(e ^ 0x80000000u)
                             : __uint_as_float(~e);
}
#define ENC_NEG_INF 0x007FFFFFu   // enc_f(-inf)

// ---------------- init: zero accumulators, -inf maxes ----------------------
__global__ void init_kernel() {
    int i = blockIdx.x * blockDim.x + threadIdx.x;
    if (i < NN * DD) g_num[i] = 0.0f;
    if (i < NN * HH) { g_m[i] = ENC_NEG_INF; g_s[i] = 0.0f; }
}

// ---------------- fused 4-matrix GEMM: O_m = X @ W_m + b_m -----------------
// 128-row x 128-col tile per block, 256 threads, 8x8 register tile per thread.
// W tile + X tile both in smem (128 KB dynamic).
__global__ __launch_bounds__(256, 1) void gemm4_kernel(
    const float* __restrict__ X,
    const float* __restrict__ W0, const float* __restrict__ B0,
    const float* __restrict__ W1, const float* __restrict__ B1,
    const float* __restrict__ W2, const float* __restrict__ B2,
    const float* __restrict__ W3, const float* __restrict__ B3,
    float* O0, float* O1, float* O2, float* O3)
{
    extern __shared__ float smem[];
    float* Xs  = smem;            // [128][128]  Xs[r][k]
    float* Wsm = smem + DD * DD;  // [128][128]  Wsm[k][c]

    const float* W; const float* B; float* O;
    int m = blockIdx.y;
    if      (m == 0) { W = W0; B = B0; O = O0; }
    else if (m == 1) { W = W1; B = B1; O = O1; }
    else if (m == 2) { W = W2; B = B2; O = O2; }
    else             { W = W3; B = B3; O = O3; }

    int row0 = blockIdx.x * 128;

    // load W (row-major [k][c]) straight into smem
    const float4* W4  = (const float4*)W;
    float4*       Ws4 = (float4*)Wsm;
    for (int i = threadIdx.x; i < DD * DD / 4; i += 256) Ws4[i] = W4[i];

    // load X tile (row-major), zero-pad past N
    for (int i = threadIdx.x; i < 128 * DD / 4; i += 256) {
        int r  = i >> 5;         // 32 float4 per row
        int c4 = i & 31;
        int gr = row0 + r;
        float4 xv = make_float4(0.f, 0.f, 0.f, 0.f);
        if (gr < NN) xv = ((const float4*)(X + (size_t)gr * DD))[c4];
        ((float4*)(Xs + r * DD))[c4] = xv;
    }
    __syncthreads();

    int tx = threadIdx.x & 15, ty = threadIdx.x >> 4;
    int c0 = tx * 8, r0 = ty * 8;

    float bb[8];
#pragma unroll
    for (int j = 0; j < 8; j++) bb[j] = B[c0 + j];

    float acc[8][8];
#pragma unroll
    for (int i = 0; i < 8; i++)
#pragma unroll
        for (int j = 0; j < 8; j++) acc[i][j] = bb[j];

#pragma unroll 4
    for (int k = 0; k < DD; k++) {
        float xr[8];
#pragma unroll
        for (int i = 0; i < 8; i++) xr[i] = Xs[(r0 + i) * DD + k];  // smem broadcast
        float4 wa = *(const float4*)(Wsm + k * DD + c0);
        float4 wb = *(const float4*)(Wsm + k * DD + c0 + 4);
        float wc[8] = {wa.x, wa.y, wa.z, wa.w, wb.x, wb.y, wb.z, wb.w};
#pragma unroll
        for (int i = 0; i < 8; i++)
#pragma unroll
            for (int j = 0; j < 8; j++) acc[i][j] += xr[i] * wc[j];
    }

#pragma unroll
    for (int i = 0; i < 8; i++) {
        int gr = row0 + r0 + i;
        if (gr < NN) {
            float4* op = (float4*)(O + (size_t)gr * DD + c0);
            op[0] = make_float4(acc[i][0], acc[i][1], acc[i][2], acc[i][3]);
            op[1] = make_float4(acc[i][4], acc[i][5], acc[i][6], acc[i][7]);
        }
    }
}

// ---------------- edge pass 1: score + segment max -------------------------
// one warp per edge; lane l covers dims [4l, 4l+4), head = l/4
__global__ __launch_bounds__(256) void edge_score_kernel(
    const int* __restrict__ ei,
    const float* __restrict__ q, const float* __restrict__ k,
    float* __restrict__ score, unsigned* __restrict__ mmax)
{
    int gt = blockIdx.x * blockDim.x + threadIdx.x;
    int e = gt >> 5;
    if (e >= EE) return;
    int lane = threadIdx.x & 31;

    int s = ei[e];
    int d = ei[EE + e];

    float4 qv = ((const float4*)(q + (size_t)d * DD))[lane];
    float4 kv = ((const float4*)(k + (size_t)s * DD))[lane];
    float p = qv.x * kv.x + qv.y * kv.y + qv.z * kv.z + qv.w * kv.w;
    p += __shfl_xor_sync(0xFFFFFFFFu, p, 1);
    p += __shfl_xor_sync(0xFFFFFFFFu, p, 2);

    if ((lane & 3) == 0) {
        int hh = lane >> 2;
        float sc = p * SCALE_ATT;
        score[(size_t)e * HH + hh] = sc;
        atomicMax(&mmax[d * HH + hh], enc_f(sc));
    }
}

// ---------------- edge pass 2: exp-weight, denom sum, weighted-V scatter ---
__global__ __launch_bounds__(256) void edge_agg_kernel(
    const int* __restrict__ ei,
    const float* __restrict__ score, const unsigned* __restrict__ mmax,
    const float* __restrict__ v,
    float* __restrict__ ssum, float* __restrict__ num)
{
    int gt = blockIdx.x * blockDim.x + threadIdx.x;
    int e = gt >> 5;
    if (e >= EE) return;
    int lane = threadIdx.x & 31;

    int s = ei[e];
    int d = ei[EE + e];

    int hh = lane >> 2;
    float sc = score[(size_t)e * HH + hh];
    float mv = dec_f(mmax[d * HH + hh]);
    float w = __expf(sc - mv);

    if ((lane & 3) == 0) atomicAdd(&ssum[d * HH + hh], w);

    float4 vv = ((const float4*)(v + (size_t)s * DD))[lane];
    float* p = num + (size_t)d * DD + lane * 4;
    asm volatile("red.global.add.v4.f32 [%0], {%1,%2,%3,%4};"
                 :: "l"(p), "f"(w * vv.x), "f"(w * vv.y),
                    "f"(w * vv.z), "f"(w * vv.w)
                 : "memory");
}

// ---------------- finalize: out = prelu(num/s + skip [+ resid]) ------------
__global__ __launch_bounds__(256) void finalize_kernel(
    const float* __restrict__ num, const float* __restrict__ ssum,
    const float* __restrict__ skip, const float* __restrict__ resid,
    const float* __restrict__ a_ptr, float* __restrict__ out)
{
    int i = blockIdx.x * blockDim.x + threadIdx.x;
    if (i >= NN * DD) return;
    int n = i >> 7;
    int hh = (i >> 4) & 7;
    float sv = ssum[n * HH + hh];
    float agg = (sv > 0.f) ? num[i] / sv : 0.f;   // isolated nodes -> 0
    float y = agg + skip[i];
    if (resid) y += resid[i];
    float a = *a_ptr;
    out[i] = (y >= 0.f) ? y : a * y;
}

// ---------------- host launch ----------------------------------------------
extern "C" void kernel_launch(void* const* d_in, const int* in_sizes, int n_in,
                              void* d_out, int out_size)
{
    (void)in_sizes; (void)n_in; (void)out_size;
    const float* x   = (const float*)d_in[0];
    const int*   ei  = (const int*)d_in[1];     // int32 (jax x64 disabled)
    const float* a   = (const float*)d_in[2];
    const float* Wq1 = (const float*)d_in[3];  const float* bq1 = (const float*)d_in[4];
    const float* Wk1 = (const float*)d_in[5];  const float* bk1 = (const float*)d_in[6];
    const float* Wv1 = (const float*)d_in[7];  const float* bv1 = (const float*)d_in[8];
    const float* Ws1 = (const float*)d_in[9];  const float* bs1 = (const float*)d_in[10];
    const float* Wq2 = (const float*)d_in[11]; const float* bq2 = (const float*)d_in[12];
    const float* Wk2 = (const float*)d_in[13]; const float* bk2 = (const float*)d_in[14];
    const float* Wv2 = (const float*)d_in[15]; const float* bv2 = (const float*)d_in[16];
    const float* Ws2 = (const float*)d_in[17]; const float* bs2 = (const float*)d_in[18];
    float* out = (float*)d_out;

    float *qp, *kp, *vp, *skp, *hp, *np, *scp, *ssp; unsigned* mp;
    cudaGetSymbolAddress((void**)&qp,  g_q);
    cudaGetSymbolAddress((void**)&kp,  g_k);
    cudaGetSymbolAddress((void**)&vp,  g_v);
    cudaGetSymbolAddress((void**)&skp, g_skip);
    cudaGetSymbolAddress((void**)&hp,  g_h);
    cudaGetSymbolAddress((void**)&np,  g_num);
    cudaGetSymbolAddress((void**)&scp, g_score);
    cudaGetSymbolAddress((void**)&ssp, g_s);
    cudaGetSymbolAddress((void**)&mp,  g_m);

    const int smemBytes = 2 * DD * DD * (int)sizeof(float);  // 128 KB
    cudaFuncSetAttribute(gemm4_kernel,
                         cudaFuncAttributeMaxDynamicSharedMemorySize, smemBytes);

    dim3 ggrid((NN + 127) / 128, 4);
    int initBlocks = (NN * DD + 255) / 256;
    int edgeBlocks = (int)(((long long)EE * 32 + 255) / 256);
    int finBlocks  = (NN * DD + 255) / 256;

    // ---- layer 1 ----
    init_kernel<<<initBlocks, 256>>>();
    gemm4_kernel<<<ggrid, 256, smemBytes>>>(x,
        Wq1, bq1, Wk1, bk1, Wv1, bv1, Ws1, bs1, qp, kp, vp, skp);
    edge_score_kernel<<<edgeBlocks, 256>>>(ei, qp, kp, scp, mp);
    edge_agg_kernel<<<edgeBlocks, 256>>>(ei, scp, mp, vp, ssp, np);
    finalize_kernel<<<finBlocks, 256>>>(np, ssp, skp, nullptr, a, hp); // prelu(h1)

    // ---- layer 2 ----
    init_kernel<<<initBlocks, 256>>>();
    gemm4_kernel<<<ggrid, 256, smemBytes>>>(hp,
        Wq2, bq2, Wk2, bk2, Wv2, bv2, Ws2, bs2, qp, kp, vp, skp);
    edge_score_kernel<<<edgeBlocks, 256>>>(ei, qp, kp, scp, mp);
    edge_agg_kernel<<<edgeBlocks, 256>>>(ei, scp, mp, vp, ssp, np);
    finalize_kernel<<<finBlocks, 256>>>(np, ssp, skp, x, a, out);     // prelu(h2+x)
}

// round 3
// speedup vs baseline: 1.2767x; 1.2767x over previous
#include <cuda_runtime.h>
#include <cstdint>
#include <cstddef>

#define NN 100000
#define EE 1000000
#define DD 128
#define HH 8
#define SCALE_ATT 0.25f   // 1/sqrt(16)
#define LDS_PAD 132       // smem row stride (floats): bank = (4*row + col) % 32

// ---------------- scratch (static device globals; no allocation allowed) ----
__device__ float    g_q[NN * DD];
__device__ float    g_k[NN * DD];
__device__ float    g_v[NN * DD];
__device__ float    g_skip[NN * DD];
__device__ float    g_h[NN * DD];
__device__ float    g_num[NN * DD];
__device__ float    g_score[(size_t)EE * HH];
__device__ unsigned g_m[NN * HH];     // order-encoded float max
__device__ float    g_s[NN * HH];

__device__ __forceinline__ unsigned enc_f(float f) {
    unsigned u = __float_as_uint(f);
    return (u & 0x80000000u) ? ~u : (u | 0x80000000u);
}
__device__ __forceinline__ float dec_f(unsigned e) {
    return (e & 0x80000000u) ? __uint_as_float(e ^ 0x80000000u)
                             : __uint_as_float(~e);
}
#define ENC_NEG_INF 0x007FFFFFu   // enc_f(-inf)

__device__ __forceinline__ float tf32r(float x) {
    uint32_t u;
    asm("cvt.rna.tf32.f32 %0, %1;" : "=r"(u) : "f"(x));
    return __uint_as_float(u);
}

// ---------------- init -----------------------------------------------------
__global__ void init_kernel() {
    int i = blockIdx.x * blockDim.x + threadIdx.x;
    if (i < NN * DD) g_num[i] = 0.0f;
    if (i < NN * HH) { g_m[i] = ENC_NEG_INF; g_s[i] = 0.0f; }
}

// ---------------- fused 4-matrix GEMM, tf32 tensor-core --------------------
// 128x128 tile per block, 256 threads = 8 warps (4 row x 2 col),
// each warp: 32 rows x 64 cols = 2 x 8 m16n8 tiles, K in 16 steps of 8.
__global__ __launch_bounds__(256, 1) void gemm4_tc_kernel(
    const float* __restrict__ X,
    const float* __restrict__ W0, const float* __restrict__ B0,
    const float* __restrict__ W1, const float* __restrict__ B1,
    const float* __restrict__ W2, const float* __restrict__ B2,
    const float* __restrict__ W3, const float* __restrict__ B3,
    float* O0, float* O1, float* O2, float* O3)
{
    extern __shared__ float smem[];
    float* Xs = smem;                 // [128][LDS_PAD]  Xs[r][k], tf32-rounded
    float* Wt = smem + DD * LDS_PAD;  // [128][LDS_PAD]  Wt[c][k], tf32-rounded

    const float* W; const float* B; float* O;
    int m = blockIdx.y;
    if      (m == 0) { W = W0; B = B0; O = O0; }
    else if (m == 1) { W = W1; B = B1; O = O1; }
    else if (m == 2) { W = W2; B = B2; O = O2; }
    else             { W = W3; B = B3; O = O3; }

    int row0 = blockIdx.x * 128;
    int tid = threadIdx.x;

    // load W[k][c] transposed -> Wt[c][k]  (coalesced gmem reads, scalar stores)
    for (int i = tid; i < DD * DD; i += 256) {
        int k = i >> 7, c = i & 127;
        Wt[c * LDS_PAD + k] = tf32r(W[k * DD + c]);
    }
    // load X tile -> Xs[r][k], zero-pad past N
    for (int i = tid; i < 128 * DD / 4; i += 256) {
        int r  = i >> 5;
        int c4 = (i & 31) * 4;
        int gr = row0 + r;
        float4 xv = make_float4(0.f, 0.f, 0.f, 0.f);
        if (gr < NN) xv = ((const float4*)(X + (size_t)gr * DD))[i & 31];
        float* p = Xs + r * LDS_PAD + c4;
        p[0] = tf32r(xv.x); p[1] = tf32r(xv.y);
        p[2] = tf32r(xv.z); p[3] = tf32r(xv.w);
    }
    __syncthreads();

    int warp = tid >> 5, lane = tid & 31;
    int wr = warp >> 1, wc = warp & 1;        // 4 x 2 warp grid
    int rbase = wr * 32, cbase = wc * 64;
    int lr = lane >> 2, lk = lane & 3;        // lane row-group / k-group

    // accumulators, bias-initialized
    float acc[2][8][4];
#pragma unroll
    for (int nt = 0; nt < 8; nt++) {
        int col = cbase + nt * 8 + 2 * lk;
        float b0 = B[col], b1 = B[col + 1];
#pragma unroll
        for (int mt = 0; mt < 2; mt++) {
            acc[mt][nt][0] = b0; acc[mt][nt][1] = b1;
            acc[mt][nt][2] = b0; acc[mt][nt][3] = b1;
        }
    }

#pragma unroll
    for (int ks = 0; ks < 16; ks++) {
        int k0 = ks * 8;
        // A fragments (2 m16 tiles)
        uint32_t a[2][4];
#pragma unroll
        for (int mt = 0; mt < 2; mt++) {
            const float* base = Xs + (rbase + mt * 16 + lr) * LDS_PAD + k0 + lk;
            a[mt][0] = __float_as_uint(base[0]);
            a[mt][1] = __float_as_uint(base[8 * LDS_PAD]);
            a[mt][2] = __float_as_uint(base[4]);
            a[mt][3] = __float_as_uint(base[8 * LDS_PAD + 4]);
        }
#pragma unroll
        for (int nt = 0; nt < 8; nt++) {
            const float* bbase = Wt + (cbase + nt * 8 + lr) * LDS_PAD + k0 + lk;
            uint32_t b0 = __float_as_uint(bbase[0]);
            uint32_t b1 = __float_as_uint(bbase[4]);
#pragma unroll
            for (int mt = 0; mt < 2; mt++) {
                asm volatile(
                    "mma.sync.aligned.m16n8k8.row.col.f32.tf32.tf32.f32 "
                    "{%0,%1,%2,%3}, {%4,%5,%6,%7}, {%8,%9}, {%0,%1,%2,%3};"
                    : "+f"(acc[mt][nt][0]), "+f"(acc[mt][nt][1]),
                      "+f"(acc[mt][nt][2]), "+f"(acc[mt][nt][3])
                    : "r"(a[mt][0]), "r"(a[mt][1]), "r"(a[mt][2]), "r"(a[mt][3]),
                      "r"(b0), "r"(b1));
            }
        }
    }

    // store C
#pragma unroll
    for (int mt = 0; mt < 2; mt++) {
        int gr0 = row0 + rbase + mt * 16 + lr;
        int gr1 = gr0 + 8;
#pragma unroll
        for (int nt = 0; nt < 8; nt++) {
            int col = cbase + nt * 8 + 2 * lk;
            if (gr0 < NN)
                *(float2*)(O + (size_t)gr0 * DD + col) =
                    make_float2(acc[mt][nt][0], acc[mt][nt][1]);
            if (gr1 < NN)
                *(float2*)(O + (size_t)gr1 * DD + col) =
                    make_float2(acc[mt][nt][2], acc[mt][nt][3]);
        }
    }
}

// ---------------- edge pass 1: score + segment max -------------------------
__global__ __launch_bounds__(256) void edge_score_kernel(
    const int* __restrict__ ei,
    const float* __restrict__ q, const float* __restrict__ k,
    float* __restrict__ score, unsigned* __restrict__ mmax)
{
    int gt = blockIdx.x * blockDim.x + threadIdx.x;
    int e = gt >> 5;
    if (e >= EE) return;
    int lane = threadIdx.x & 31;

    int s = ei[e];
    int d = ei[EE + e];

    float4 qv = ((const float4*)(q + (size_t)d * DD))[lane];
    float4 kv = ((const float4*)(k + (size_t)s * DD))[lane];
    float p = qv.x * kv.x + qv.y * kv.y + qv.z * kv.z + qv.w * kv.w;
    p += __shfl_xor_sync(0xFFFFFFFFu, p, 1);
    p += __shfl_xor_sync(0xFFFFFFFFu, p, 2);

    if ((lane & 3) == 0) {
        int hh = lane >> 2;
        float sc = p * SCALE_ATT;
        score[(size_t)e * HH + hh] = sc;
        atomicMax(&mmax[d * HH + hh], enc_f(sc));
    }
}

// ---------------- edge pass 2: exp-weight, denom sum, weighted-V scatter ---
__global__ __launch_bounds__(256) void edge_agg_kernel(
    const int* __restrict__ ei,
    const float* __restrict__ score, const unsigned* __restrict__ mmax,
    const float* __restrict__ v,
    float* __restrict__ ssum, float* __restrict__ num)
{
    int gt = blockIdx.x * blockDim.x + threadIdx.x;
    int e = gt >> 5;
    if (e >= EE) return;
    int lane = threadIdx.x & 31;

    int s = ei[e];
    int d = ei[EE + e];

    int hh = lane >> 2;
    float sc = score[(size_t)e * HH + hh];
    float mv = dec_f(mmax[d * HH + hh]);
    float w = __expf(sc - mv);

    if ((lane & 3) == 0) atomicAdd(&ssum[d * HH + hh], w);

    float4 vv = ((const float4*)(v + (size_t)s * DD))[lane];
    float* p = num + (size_t)d * DD + lane * 4;
    asm volatile("red.global.add.v4.f32 [%0], {%1,%2,%3,%4};"
                 :: "l"(p), "f"(w * vv.x), "f"(w * vv.y),
                    "f"(w * vv.z), "f"(w * vv.w)
                 : "memory");
}

// ---------------- finalize: out = prelu(num/s + skip [+ resid]) ------------
__global__ __launch_bounds__(256) void finalize_kernel(
    const float* __restrict__ num, const float* __restrict__ ssum,
    const float* __restrict__ skip, const float* __restrict__ resid,
    const float* __restrict__ a_ptr, float* __restrict__ out)
{
    int i = blockIdx.x * blockDim.x + threadIdx.x;
    if (i >= NN * DD) return;
    int n = i >> 7;
    int hh = (i >> 4) & 7;
    float sv = ssum[n * HH + hh];
    float agg = (sv > 0.f) ? num[i] / sv : 0.f;
    float y = agg + skip[i];
    if (resid) y += resid[i];
    float a = *a_ptr;
    out[i] = (y >= 0.f) ? y : a * y;
}

// ---------------- host launch ----------------------------------------------
extern "C" void kernel_launch(void* const* d_in, const int* in_sizes, int n_in,
                              void* d_out, int out_size)
{
    (void)in_sizes; (void)n_in; (void)out_size;
    const float* x   = (const float*)d_in[0];
    const int*   ei  = (const int*)d_in[1];
    const float* a   = (const float*)d_in[2];
    const float* Wq1 = (const float*)d_in[3];  const float* bq1 = (const float*)d_in[4];
    const float* Wk1 = (const float*)d_in[5];  const float* bk1 = (const float*)d_in[6];
    const float* Wv1 = (const float*)d_in[7];  const float* bv1 = (const float*)d_in[8];
    const float* Ws1 = (const float*)d_in[9];  const float* bs1 = (const float*)d_in[10];
    const float* Wq2 = (const float*)d_in[11]; const float* bq2 = (const float*)d_in[12];
    const float* Wk2 = (const float*)d_in[13]; const float* bk2 = (const float*)d_in[14];
    const float* Wv2 = (const float*)d_in[15]; const float* bv2 = (const float*)d_in[16];
    const float* Ws2 = (const float*)d_in[17]; const float* bs2 = (const float*)d_in[18];
    float* out = (float*)d_out;

    float *qp, *kp, *vp, *skp, *hp, *np, *scp, *ssp; unsigned* mp;
    cudaGetSymbolAddress((void**)&qp,  g_q);
    cudaGetSymbolAddress((void**)&kp,  g_k);
    cudaGetSymbolAddress((void**)&vp,  g_v);
    cudaGetSymbolAddress((void**)&skp, g_skip);
    cudaGetSymbolAddress((void**)&hp,  g_h);
    cudaGetSymbolAddress((void**)&np,  g_num);
    cudaGetSymbolAddress((void**)&scp, g_score);
    cudaGetSymbolAddress((void**)&ssp, g_s);
    cudaGetSymbolAddress((void**)&mp,  g_m);

    const int smemBytes = 2 * DD * LDS_PAD * (int)sizeof(float);  // ~132 KB
    cudaFuncSetAttribute(gemm4_tc_kernel,
                         cudaFuncAttributeMaxDynamicSharedMemorySize, smemBytes);

    dim3 ggrid((NN + 127) / 128, 4);
    int initBlocks = (NN * DD + 255) / 256;
    int edgeBlocks = (int)(((long long)EE * 32 + 255) / 256);
    int finBlocks  = (NN * DD + 255) / 256;

    // ---- layer 1 ----
    init_kernel<<<initBlocks, 256>>>();
    gemm4_tc_kernel<<<ggrid, 256, smemBytes>>>(x,
        Wq1, bq1, Wk1, bk1, Wv1, bv1, Ws1, bs1, qp, kp, vp, skp);
    edge_score_kernel<<<edgeBlocks, 256>>>(ei, qp, kp, scp, mp);
    edge_agg_kernel<<<edgeBlocks, 256>>>(ei, scp, mp, vp, ssp, np);
    finalize_kernel<<<finBlocks, 256>>>(np, ssp, skp, nullptr, a, hp);

    // ---- layer 2 ----
    init_kernel<<<initBlocks, 256>>>();
    gemm4_tc_kernel<<<ggrid, 256, smemBytes>>>(hp,
        Wq2, bq2, Wk2, bk2, Wv2, bv2, Ws2, bs2, qp, kp, vp, skp);
    edge_score_kernel<<<edgeBlocks, 256>>>(ei, qp, kp, scp, mp);
    edge_agg_kernel<<<edgeBlocks, 256>>>(ei, scp, mp, vp, ssp, np);
    finalize_kernel<<<finBlocks, 256>>>(np, ssp, skp, x, a, out);
}

// round 5
// speedup vs baseline: 2.0099x; 1.5743x over previous
#include <cuda_runtime.h>
#include <cstdint>
#include <cstddef>

#define NN 100000
#define EE 1000000
#define DD 128
#define HH 8
#define SCALE_ATT 0.25f   // 1/sqrt(16)
#define LDS_PAD 132       // smem row stride (floats): bank = (4*row + k) % 32

// ---------------- scratch (static device globals) --------------------------
__device__ float g_xt[NN * DD];        // tf32-rounded activations (layer input)
__device__ float g_wt[8 * DD * DD];    // tf32-rounded, transposed weights Wt[c][k]
__device__ float g_q[NN * DD];
__device__ float g_k[NN * DD];
__device__ float g_v[NN * DD];
__device__ float g_skip[NN * DD];
__device__ float g_h[NN * DD];
__device__ float g_num[NN * DD];
__device__ float g_s[NN * HH];

__device__ __forceinline__ float tf32r(float x) {
    uint32_t u;
    asm("cvt.rna.tf32.f32 %0, %1;" : "=r"(u) : "f"(x));
    return __uint_as_float(u);
}

#define CP_ASYNC16(dst_u32, src_ptr) \
    asm volatile("cp.async.cg.shared.global [%0], [%1], 16;" \
                 :: "r"(dst_u32), "l"(src_ptr))
#define CP_ASYNC_COMMIT() asm volatile("cp.async.commit_group;")
#define CP_ASYNC_WAIT0()  asm volatile("cp.async.wait_group 0;")

// ---------------- init: zero accumulators ----------------------------------
__global__ void init_kernel() {
    int i = blockIdx.x * blockDim.x + threadIdx.x;
    if (i < NN * DD / 4) ((float4*)g_num)[i] = make_float4(0.f, 0.f, 0.f, 0.f);
    if (i < NN * HH) g_s[i] = 0.0f;
}

// ---------------- prep W: transpose + tf32-round all 8 weight matrices -----
__global__ void prep_w_kernel(
    const float* __restrict__ W0, const float* __restrict__ W1,
    const float* __restrict__ W2, const float* __restrict__ W3,
    const float* __restrict__ W4, const float* __restrict__ W5,
    const float* __restrict__ W6, const float* __restrict__ W7)
{
    const float* Ws[8] = {W0, W1, W2, W3, W4, W5, W6, W7};
    int m = blockIdx.z;
    const float* W = Ws[m];
    __shared__ float t[32][33];
    int k0 = blockIdx.x * 32, c0 = blockIdx.y * 32;
    int tx = threadIdx.x, ty = threadIdx.y;
#pragma unroll
    for (int i = 0; i < 4; i++)
        t[ty + 8 * i][tx] = tf32r(W[(k0 + ty + 8 * i) * DD + c0 + tx]);
    __syncthreads();
#pragma unroll
    for (int i = 0; i < 4; i++)
        g_wt[m * DD * DD + (c0 + ty + 8 * i) * DD + k0 + tx] = t[tx][ty + 8 * i];
}

// ---------------- prep X: tf32-round activations ---------------------------
__global__ void prep_x_kernel(const float* __restrict__ X) {
    int i = blockIdx.x * blockDim.x + threadIdx.x;
    if (i >= NN * DD / 4) return;
    float4 v = ((const float4*)X)[i];
    v.x = tf32r(v.x); v.y = tf32r(v.y); v.z = tf32r(v.z); v.w = tf32r(v.w);
    ((float4*)g_xt)[i] = v;
}

// ---------------- fused 4-matrix tf32 GEMM ---------------------------------
// 128x128 tile, 512 threads = 16 warps (4x4), warp tile 32x32 (2x4 m16n8).
// X from g_xt (pre-rounded), W from g_wt (pre-rounded+transposed).
// wofs selects the weight bank: layer1 -> 0, layer2 -> 4.
__global__ __launch_bounds__(512, 1) void gemm4_tc_kernel(
    int wofs,
    const float* __restrict__ B0, const float* __restrict__ B1,
    const float* __restrict__ B2, const float* __restrict__ B3,
    float* O0, float* O1, float* O2, float* O3)
{
    extern __shared__ float smem[];
    float* Xs = smem;                 // [128][LDS_PAD]  Xs[r][k]
    float* Ws = smem + DD * LDS_PAD;  // [128][LDS_PAD]  Ws[c][k]

    int m = blockIdx.y;
    const float* B; float* O;
    if      (m == 0) { B = B0; O = O0; }
    else if (m == 1) { B = B1; O = O1; }
    else if (m == 2) { B = B2; O = O2; }
    else             { B = B3; O = O3; }
    const float* Wt = g_wt + (size_t)(wofs + m) * DD * DD;

    int row0 = blockIdx.x * 128;
    int tid = threadIdx.x;

    // async-copy both tiles (float4 granularity; rows past N clamp-duplicate)
    uint32_t xs_b = (uint32_t)__cvta_generic_to_shared(Xs);
    uint32_t ws_b = (uint32_t)__cvta_generic_to_shared(Ws);
#pragma unroll
    for (int it = 0; it < 8; it++) {
        int i = tid + it * 512;               // 0..4095
        int r = i >> 5, c4 = (i & 31) * 4;
        int gr = row0 + r; if (gr >= NN) gr = NN - 1;
        CP_ASYNC16(xs_b + (r * LDS_PAD + c4) * 4, g_xt + (size_t)gr * DD + c4);
        CP_ASYNC16(ws_b + (r * LDS_PAD + c4) * 4, Wt + (size_t)r * DD + c4);
    }
    CP_ASYNC_COMMIT();

    int warp = tid >> 5, lane = tid & 31;
    int rbase = (warp >> 2) * 32, cbase = (warp & 3) * 32;
    int lr = lane >> 2, lk = lane & 3;

    float acc[2][4][4];
#pragma unroll
    for (int nt = 0; nt < 4; nt++) {
        int col = cbase + nt * 8 + 2 * lk;
        float b0v = B[col], b1v = B[col + 1];
#pragma unroll
        for (int mt = 0; mt < 2; mt++) {
            acc[mt][nt][0] = b0v; acc[mt][nt][1] = b1v;
            acc[mt][nt][2] = b0v; acc[mt][nt][3] = b1v;
        }
    }

    CP_ASYNC_WAIT0();
    __syncthreads();

#pragma unroll
    for (int ks = 0; ks < 16; ks++) {
        int k0 = ks * 8;
        uint32_t a[2][4];
#pragma unroll
        for (int mt = 0; mt < 2; mt++) {
            const float* base = Xs + (rbase + mt * 16 + lr) * LDS_PAD + k0 + lk;
            a[mt][0] = __float_as_uint(base[0]);
            a[mt][1] = __float_as_uint(base[8 * LDS_PAD]);
            a[mt][2] = __float_as_uint(base[4]);
            a[mt][3] = __float_as_uint(base[8 * LDS_PAD + 4]);
        }
#pragma unroll
        for (int nt = 0; nt < 4; nt++) {
            const float* bbase = Ws + (cbase + nt * 8 + lr) * LDS_PAD + k0 + lk;
            uint32_t b0 = __float_as_uint(bbase[0]);
            uint32_t b1 = __float_as_uint(bbase[4]);
#pragma unroll
            for (int mt = 0; mt < 2; mt++) {
                asm volatile(
                    "mma.sync.aligned.m16n8k8.row.col.f32.tf32.tf32.f32 "
                    "{%0,%1,%2,%3}, {%4,%5,%6,%7}, {%8,%9}, {%0,%1,%2,%3};"
                    : "+f"(acc[mt][nt][0]), "+f"(acc[mt][nt][1]),
                      "+f"(acc[mt][nt][2]), "+f"(acc[mt][nt][3])
                    : "r"(a[mt][0]), "r"(a[mt][1]), "r"(a[mt][2]), "r"(a[mt][3]),
                      "r"(b0), "r"(b1));
            }
        }
    }

#pragma unroll
    for (int mt = 0; mt < 2; mt++) {
        int gr0 = row0 + rbase + mt * 16 + lr;
        int gr1 = gr0 + 8;
#pragma unroll
        for (int nt = 0; nt < 4; nt++) {
            int col = cbase + nt * 8 + 2 * lk;
            if (gr0 < NN)
                *(float2*)(O + (size_t)gr0 * DD + col) =
                    make_float2(acc[mt][nt][0], acc[mt][nt][1]);
            if (gr1 < NN)
                *(float2*)(O + (size_t)gr1 * DD + col) =
                    make_float2(acc[mt][nt][2], acc[mt][nt][3]);
        }
    }
}

// ---------------- fused edge pass: score, exp, denom + weighted-V scatter --
// one warp per edge; lane l covers dims [4l,4l+4), head = l/4. No max shift:
// alpha = exp(s)/sum exp(s) is exact; |score| stays far below exp overflow.
__global__ __launch_bounds__(256) void edge_attn_kernel(
    const int* __restrict__ ei,
    const float* __restrict__ q, const float* __restrict__ k,
    const float* __restrict__ v,
    float* __restrict__ ssum, float* __restrict__ num)
{
    int gt = blockIdx.x * blockDim.x + threadIdx.x;
    int e = gt >> 5;
    if (e >= EE) return;
    int lane = threadIdx.x & 31;

    int s = ei[e];
    int d = ei[EE + e];

    float4 qv = ((const float4*)(q + (size_t)d * DD))[lane];
    float4 kv = ((const float4*)(k + (size_t)s * DD))[lane];
    float p = qv.x * kv.x + qv.y * kv.y + qv.z * kv.z + qv.w * kv.w;
    p += __shfl_xor_sync(0xFFFFFFFFu, p, 1);
    p += __shfl_xor_sync(0xFFFFFFFFu, p, 2);

    int hh = lane >> 2;
    float w = __expf(p * SCALE_ATT);

    if ((lane & 3) == 0) atomicAdd(&ssum[d * HH + hh], w);

    float4 vv = ((const float4*)(v + (size_t)s * DD))[lane];
    float* pdst = num + (size_t)d * DD + lane * 4;
    asm volatile("red.global.add.v4.f32 [%0], {%1,%2,%3,%4};"
                 :: "l"(pdst), "f"(w * vv.x), "f"(w * vv.y),
                    "f"(w * vv.z), "f"(w * vv.w)
                 : "memory");
}

// ---------------- finalize: out = prelu(num/s + skip [+ resid]) ------------
__global__ __launch_bounds__(256) void finalize_kernel(
    const float* __restrict__ num, const float* __restrict__ ssum,
    const float* __restrict__ skip, const float* __restrict__ resid,
    const float* __restrict__ a_ptr, float* __restrict__ out)
{
    int i = blockIdx.x * blockDim.x + threadIdx.x;
    if (i >= NN * DD) return;
    int n = i >> 7;
    int hh = (i >> 4) & 7;
    float sv = ssum[n * HH + hh];
    float agg = (sv > 0.f) ? num[i] / sv : 0.f;
    float y = agg + skip[i];
    if (resid) y += resid[i];
    float a = *a_ptr;
    out[i] = (y >= 0.f) ? y : a * y;
}

// ---------------- host launch ----------------------------------------------
extern "C" void kernel_launch(void* const* d_in, const int* in_sizes, int n_in,
                              void* d_out, int out_size)
{
    (void)in_sizes; (void)n_in; (void)out_size;
    const float* x   = (const float*)d_in[0];
    const int*   ei  = (const int*)d_in[1];
    const float* a   = (const float*)d_in[2];
    const float* Wq1 = (const float*)d_in[3];  const float* bq1 = (const float*)d_in[4];
    const float* Wk1 = (const float*)d_in[5];  const float* bk1 = (const float*)d_in[6];
    const float* Wv1 = (const float*)d_in[7];  const float* bv1 = (const float*)d_in[8];
    const float* Ws1 = (const float*)d_in[9];  const float* bs1 = (const float*)d_in[10];
    const float* Wq2 = (const float*)d_in[11]; const float* bq2 = (const float*)d_in[12];
    const float* Wk2 = (const float*)d_in[13]; const float* bk2 = (const float*)d_in[14];
    const float* Wv2 = (const float*)d_in[15]; const float* bv2 = (const float*)d_in[16];
    const float* Ws2 = (const float*)d_in[17]; const float* bs2 = (const float*)d_in[18];
    float* out = (float*)d_out;

    float *qp, *kp, *vp, *skp, *hp, *np, *ssp;
    cudaGetSymbolAddress((void**)&qp,  g_q);
    cudaGetSymbolAddress((void**)&kp,  g_k);
    cudaGetSymbolAddress((void**)&vp,  g_v);
    cudaGetSymbolAddress((void**)&skp, g_skip);
    cudaGetSymbolAddress((void**)&hp,  g_h);
    cudaGetSymbolAddress((void**)&np,  g_num);
    cudaGetSymbolAddress((void**)&ssp, g_s);

    const int smemBytes = 2 * DD * LDS_PAD * (int)sizeof(float);  // ~132 KB
    cudaFuncSetAttribute(gemm4_tc_kernel,
                         cudaFuncAttributeMaxDynamicSharedMemorySize, smemBytes);

    dim3 ggrid((NN + 127) / 128, 4);
    dim3 wgrid(4, 4, 8);
    int initBlocks = (NN * DD / 4 + 255) / 256;
    int prepBlocks = (NN * DD / 4 + 255) / 256;
    int edgeBlocks = (int)(((long long)EE * 32 + 255) / 256);
    int finBlocks  = (NN * DD + 255) / 256;

    // one-time: transpose + round all 8 weight matrices
    prep_w_kernel<<<wgrid, dim3(32, 8)>>>(Wq1, Wk1, Wv1, Ws1, Wq2, Wk2, Wv2, Ws2);

    // ---- layer 1 ----
    init_kernel<<<initBlocks, 256>>>();
    prep_x_kernel<<<prepBlocks, 256>>>(x);
    gemm4_tc_kernel<<<ggrid, 512, smemBytes>>>(0, bq1, bk1, bv1, bs1, qp, kp, vp, skp);
    edge_attn_kernel<<<edgeBlocks, 256>>>(ei, qp, kp, vp, ssp, np);
    finalize_kernel<<<finBlocks, 256>>>(np, ssp, skp, nullptr, a, hp);

    // ---- layer 2 ----
    init_kernel<<<initBlocks, 256>>>();
    prep_x_kernel<<<prepBlocks, 256>>>(hp);
    gemm4_tc_kernel<<<ggrid, 512, smemBytes>>>(4, bq2, bk2, bv2, bs2, qp, kp, vp, skp);
    edge_attn_kernel<<<edgeBlocks, 256>>>(ei, qp, kp, vp, ssp, np);
    finalize_kernel<<<finBlocks, 256>>>(np, ssp, skp, x, a, out);
}

// round 6
// speedup vs baseline: 3.4298x; 1.7065x over previous
#include <cuda_runtime.h>
#include <cstdint>
#include <cstddef>

#define NN 100000
#define EE 1000000
#define DD 128
#define HH 8
#define SCALE_ATT 0.25f   // 1/sqrt(16)
#define LDS_PAD 132       // smem row stride (floats): bank = (4*row + k) % 32
#define NB 98             // scan blocks of 1024 covering NN (+1)

// ---------------- scratch (static device globals) --------------------------
__device__ float g_xt[NN * DD];        // tf32-rounded activations (GEMM input)
__device__ float g_wt[8 * DD * DD];    // tf32-rounded, transposed weights Wt[c][k]
__device__ float g_q[NN * DD];
__device__ float g_k[NN * DD];
__device__ float g_v[NN * DD];
__device__ float g_skip[NN * DD];
__device__ int   g_deg[NN];
__device__ int   g_roff[NN + 1];
__device__ int   g_mut[NN];
__device__ int   g_csr[EE];
__device__ int   g_bsum[NB];
__device__ int   g_bpre[NB];

__device__ __forceinline__ float tf32r(float x) {
    uint32_t u;
    asm("cvt.rna.tf32.f32 %0, %1;" : "=r"(u) : "f"(x));
    return __uint_as_float(u);
}

#define CP_ASYNC16(dst_u32, src_ptr) \
    asm volatile("cp.async.cg.shared.global [%0], [%1], 16;" \
                 :: "r"(dst_u32), "l"(src_ptr))
#define CP_ASYNC_COMMIT() asm volatile("cp.async.commit_group;")

// ================= CSR build =================
__global__ void hist_kernel(const int* __restrict__ ei) {
    int e = blockIdx.x * blockDim.x + threadIdx.x;
    if (e < EE) atomicAdd(&g_deg[ei[EE + e]], 1);
}

__global__ void csr_bsum_kernel() {
    __shared__ int sm[1024];
    int tid = threadIdx.x;
    int idx = blockIdx.x * 1024 + tid;
    sm[tid] = (idx < NN) ? g_deg[idx] : 0;
    __syncthreads();
    for (int s = 512; s > 0; s >>= 1) {
        if (tid < s) sm[tid] += sm[tid + s];
        __syncthreads();
    }
    if (tid == 0) g_bsum[blockIdx.x] = sm[0];
}

__global__ void csr_scanb_kernel() {
    __shared__ int sm[128];
    int tid = threadIdx.x;
    int v = (tid < NB) ? g_bsum[tid] : 0;
    sm[tid] = v;
    __syncthreads();
    for (int off = 1; off < 128; off <<= 1) {
        int t = (tid >= off) ? sm[tid - off] : 0;
        __syncthreads();
        sm[tid] += t;
        __syncthreads();
    }
    if (tid < NB) g_bpre[tid] = sm[tid] - v;   // exclusive
}

__global__ void csr_offsets_kernel() {
    __shared__ int sm[1024];
    int tid = threadIdx.x;
    int idx = blockIdx.x * 1024 + tid;
    int v = (idx < NN) ? g_deg[idx] : 0;
    sm[tid] = v;
    __syncthreads();
    for (int off = 1; off < 1024; off <<= 1) {
        int t = (tid >= off) ? sm[tid - off] : 0;
        __syncthreads();
        sm[tid] += t;
        __syncthreads();
    }
    int excl = sm[tid] - v + g_bpre[blockIdx.x];
    if (idx < NN) { g_roff[idx] = excl; g_mut[idx] = excl; }
    if (idx == NN) g_roff[NN] = excl;          // == EE
}

__global__ void csr_scatter_kernel(const int* __restrict__ ei) {
    int e = blockIdx.x * blockDim.x + threadIdx.x;
    if (e >= EE) return;
    int s = ei[e], d = ei[EE + e];
    int pos = atomicAdd(&g_mut[d], 1);
    g_csr[pos] = s;
}

// ================= weight / activation prep =================
__global__ void prep_w_kernel(
    const float* __restrict__ W0, const float* __restrict__ W1,
    const float* __restrict__ W2, const float* __restrict__ W3,
    const float* __restrict__ W4, const float* __restrict__ W5,
    const float* __restrict__ W6, const float* __restrict__ W7)
{
    const float* Ws[8] = {W0, W1, W2, W3, W4, W5, W6, W7};
    int m = blockIdx.z;
    const float* W = Ws[m];
    __shared__ float t[32][33];
    int k0 = blockIdx.x * 32, c0 = blockIdx.y * 32;
    int tx = threadIdx.x, ty = threadIdx.y;
#pragma unroll
    for (int i = 0; i < 4; i++)
        t[ty + 8 * i][tx] = tf32r(W[(k0 + ty + 8 * i) * DD + c0 + tx]);
    __syncthreads();
#pragma unroll
    for (int i = 0; i < 4; i++)
        g_wt[m * DD * DD + (c0 + ty + 8 * i) * DD + k0 + tx] = t[tx][ty + 8 * i];
}

__global__ void prep_x_kernel(const float* __restrict__ X) {
    int i = blockIdx.x * blockDim.x + threadIdx.x;
    if (i >= NN * DD / 4) return;
    float4 v = ((const float4*)X)[i];
    v.x = tf32r(v.x); v.y = tf32r(v.y); v.z = tf32r(v.z); v.w = tf32r(v.w);
    ((float4*)g_xt)[i] = v;
}

// ================= merged 4-matrix tf32 GEMM =================
// One block = one 128-row tile; X loaded once, loops over 4 weight matrices
// with double-buffered cp.async W prefetch. 512 threads, 16 warps (4x4).
__global__ __launch_bounds__(512, 1) void gemm_all_kernel(
    int wofs,
    const float* __restrict__ B0, const float* __restrict__ B1,
    const float* __restrict__ B2, const float* __restrict__ B3,
    float* O0, float* O1, float* O2, float* O3)
{
    extern __shared__ float smem[];
    float* Xs  = smem;                      // [128][LDS_PAD]
    float* Wb0 = smem + DD * LDS_PAD;       // [128][LDS_PAD]
    float* Wb1 = Wb0 + DD * LDS_PAD;        // [128][LDS_PAD]

    const float* Bs[4] = {B0, B1, B2, B3};
    float*       Os[4] = {O0, O1, O2, O3};

    int row0 = blockIdx.x * 128;
    int tid = threadIdx.x;

    uint32_t xs_b = (uint32_t)__cvta_generic_to_shared(Xs);
    uint32_t w0_b = (uint32_t)__cvta_generic_to_shared(Wb0);
    uint32_t w1_b = (uint32_t)__cvta_generic_to_shared(Wb1);

    const float* Wt0 = g_wt + (size_t)wofs * DD * DD;
#pragma unroll
    for (int it = 0; it < 8; it++) {
        int i = tid + it * 512;
        int r = i >> 5, c4 = (i & 31) * 4;
        int gr = row0 + r; if (gr >= NN) gr = NN - 1;
        CP_ASYNC16(xs_b + (r * LDS_PAD + c4) * 4, g_xt + (size_t)gr * DD + c4);
        CP_ASYNC16(w0_b + (r * LDS_PAD + c4) * 4, Wt0 + (size_t)r * DD + c4);
    }
    CP_ASYNC_COMMIT();

    int warp = tid >> 5, lane = tid & 31;
    int rbase = (warp >> 2) * 32, cbase = (warp & 3) * 32;
    int lr = lane >> 2, lk = lane & 3;

#pragma unroll
    for (int m = 0; m < 4; m++) {
        if (m < 3) {   // prefetch next W into the other buffer
            uint32_t dstb = ((m + 1) & 1) ? w1_b : w0_b;
            const float* Wn = g_wt + (size_t)(wofs + m + 1) * DD * DD;
#pragma unroll
            for (int it = 0; it < 8; it++) {
                int i = tid + it * 512;
                int r = i >> 5, c4 = (i & 31) * 4;
                CP_ASYNC16(dstb + (r * LDS_PAD + c4) * 4, Wn + (size_t)r * DD + c4);
            }
            CP_ASYNC_COMMIT();
            asm volatile("cp.async.wait_group 1;");
        } else {
            asm volatile("cp.async.wait_group 0;");
        }
        __syncthreads();

        const float* Ws = (m & 1) ? Wb1 : Wb0;
        const float* B = Bs[m];
        float* O = Os[m];

        float acc[2][4][4];
#pragma unroll
        for (int nt = 0; nt < 4; nt++) {
            int col = cbase + nt * 8 + 2 * lk;
            float b0v = B[col], b1v = B[col + 1];
#pragma unroll
            for (int mt = 0; mt < 2; mt++) {
                acc[mt][nt][0] = b0v; acc[mt][nt][1] = b1v;
                acc[mt][nt][2] = b0v; acc[mt][nt][3] = b1v;
            }
        }

#pragma unroll
        for (int ks = 0; ks < 16; ks++) {
            int k0 = ks * 8;
            uint32_t a[2][4];
#pragma unroll
            for (int mt = 0; mt < 2; mt++) {
                const float* base = Xs + (rbase + mt * 16 + lr) * LDS_PAD + k0 + lk;
                a[mt][0] = __float_as_uint(base[0]);
                a[mt][1] = __float_as_uint(base[8 * LDS_PAD]);
                a[mt][2] = __float_as_uint(base[4]);
                a[mt][3] = __float_as_uint(base[8 * LDS_PAD + 4]);
            }
#pragma unroll
            for (int nt = 0; nt < 4; nt++) {
                const float* bbase = Ws + (cbase + nt * 8 + lr) * LDS_PAD + k0 + lk;
                uint32_t b0 = __float_as_uint(bbase[0]);
                uint32_t b1 = __float_as_uint(bbase[4]);
#pragma unroll
                for (int mt = 0; mt < 2; mt++) {
                    asm volatile(
                        "mma.sync.aligned.m16n8k8.row.col.f32.tf32.tf32.f32 "
                        "{%0,%1,%2,%3}, {%4,%5,%6,%7}, {%8,%9}, {%0,%1,%2,%3};"
                        : "+f"(acc[mt][nt][0]), "+f"(acc[mt][nt][1]),
                          "+f"(acc[mt][nt][2]), "+f"(acc[mt][nt][3])
                        : "r"(a[mt][0]), "r"(a[mt][1]), "r"(a[mt][2]), "r"(a[mt][3]),
                          "r"(b0), "r"(b1));
                }
            }
        }

#pragma unroll
        for (int mt = 0; mt < 2; mt++) {
            int gr0 = row0 + rbase + mt * 16 + lr;
            int gr1 = gr0 + 8;
#pragma unroll
            for (int nt = 0; nt < 4; nt++) {
                int col = cbase + nt * 8 + 2 * lk;
                if (gr0 < NN)
                    *(float2*)(O + (size_t)gr0 * DD + col) =
                        make_float2(acc[mt][nt][0], acc[mt][nt][1]);
                if (gr1 < NN)
                    *(float2*)(O + (size_t)gr1 * DD + col) =
                        make_float2(acc[mt][nt][2], acc[mt][nt][3]);
            }
        }
        __syncthreads();   // protect W buffer before next prefetch overwrites
    }
}

// ================= warp-per-node attention aggregation =================
// Gathers k/v over the node's in-edges (CSR), softmax (no max shift —
// scores bounded, exp safe), normalize, add skip (+resid), PReLU, write.
// do_tf32: round output to tf32 (it feeds the next layer's GEMM).
__global__ __launch_bounds__(256) void node_attn_kernel(
    const float* __restrict__ q, const float* __restrict__ k,
    const float* __restrict__ v, const float* __restrict__ skip,
    const float* __restrict__ resid, const float* __restrict__ a_ptr,
    float* __restrict__ out, int do_tf32)
{
    int n = (blockIdx.x * blockDim.x + threadIdx.x) >> 5;
    if (n >= NN) return;
    int lane = threadIdx.x & 31;

    float4 qv = ((const float4*)(q + (size_t)n * DD))[lane];
    int j0 = g_roff[n], j1 = g_roff[n + 1];

    float4 acc = make_float4(0.f, 0.f, 0.f, 0.f);
    float ws = 0.f;

#pragma unroll 2
    for (int j = j0; j < j1; j++) {
        int s = g_csr[j];
        float4 kv = ((const float4*)(k + (size_t)s * DD))[lane];
        float p = qv.x * kv.x + qv.y * kv.y + qv.z * kv.z + qv.w * kv.w;
        p += __shfl_xor_sync(0xFFFFFFFFu, p, 1);
        p += __shfl_xor_sync(0xFFFFFFFFu, p, 2);
        float w = __expf(p * SCALE_ATT);
        ws += w;
        float4 vv = ((const float4*)(v + (size_t)s * DD))[lane];
        acc.x += w * vv.x; acc.y += w * vv.y;
        acc.z += w * vv.z; acc.w += w * vv.w;
    }

    float inv = (ws > 0.f) ? 1.f / ws : 0.f;
    float4 sk = ((const float4*)(skip + (size_t)n * DD))[lane];
    float4 y;
    y.x = acc.x * inv + sk.x;
    y.y = acc.y * inv + sk.y;
    y.z = acc.z * inv + sk.z;
    y.w = acc.w * inv + sk.w;
    if (resid) {
        float4 rv = ((const float4*)(resid + (size_t)n * DD))[lane];
        y.x += rv.x; y.y += rv.y; y.z += rv.z; y.w += rv.w;
    }
    float a = *a_ptr;
    y.x = (y.x >= 0.f) ? y.x : a * y.x;
    y.y = (y.y >= 0.f) ? y.y : a * y.y;
    y.z = (y.z >= 0.f) ? y.z : a * y.z;
    y.w = (y.w >= 0.f) ? y.w : a * y.w;
    if (do_tf32) {
        y.x = tf32r(y.x); y.y = tf32r(y.y);
        y.z = tf32r(y.z); y.w = tf32r(y.w);
    }
    ((float4*)(out + (size_t)n * DD))[lane] = y;
}

// ---------------- host launch ----------------------------------------------
extern "C" void kernel_launch(void* const* d_in, const int* in_sizes, int n_in,
                              void* d_out, int out_size)
{
    (void)in_sizes; (void)n_in; (void)out_size;
    const float* x   = (const float*)d_in[0];
    const int*   ei  = (const int*)d_in[1];
    const float* a   = (const float*)d_in[2];
    const float* Wq1 = (const float*)d_in[3];  const float* bq1 = (const float*)d_in[4];
    const float* Wk1 = (const float*)d_in[5];  const float* bk1 = (const float*)d_in[6];
    const float* Wv1 = (const float*)d_in[7];  const float* bv1 = (const float*)d_in[8];
    const float* Ws1 = (const float*)d_in[9];  const float* bs1 = (const float*)d_in[10];
    const float* Wq2 = (const float*)d_in[11]; const float* bq2 = (const float*)d_in[12];
    const float* Wk2 = (const float*)d_in[13]; const float* bk2 = (const float*)d_in[14];
    const float* Wv2 = (const float*)d_in[15]; const float* bv2 = (const float*)d_in[16];
    const float* Ws2 = (const float*)d_in[17]; const float* bs2 = (const float*)d_in[18];
    float* out = (float*)d_out;

    float *xtp, *qp, *kp, *vp, *skp; int* degp;
    cudaGetSymbolAddress((void**)&xtp, g_xt);
    cudaGetSymbolAddress((void**)&qp,  g_q);
    cudaGetSymbolAddress((void**)&kp,  g_k);
    cudaGetSymbolAddress((void**)&vp,  g_v);
    cudaGetSymbolAddress((void**)&skp, g_skip);
    cudaGetSymbolAddress((void**)&degp, g_deg);

    const int smemBytes = 3 * DD * LDS_PAD * (int)sizeof(float);  // ~203 KB
    cudaFuncSetAttribute(gemm_all_kernel,
                         cudaFuncAttributeMaxDynamicSharedMemorySize, smemBytes);

    int edgeBlocks = (EE + 255) / 256;
    int nodeBlocks = (NN * 32 + 255) / 256;
    int prepBlocks = (NN * DD / 4 + 255) / 256;
    int gemmBlocks = (NN + 127) / 128;

    // ---- CSR build (graph shared by both layers) ----
    cudaMemsetAsync(degp, 0, NN * sizeof(int));
    hist_kernel<<<edgeBlocks, 256>>>(ei);
    csr_bsum_kernel<<<NB, 1024>>>();
    csr_scanb_kernel<<<1, 128>>>();
    csr_offsets_kernel<<<NB, 1024>>>();
    csr_scatter_kernel<<<edgeBlocks, 256>>>(ei);

    // ---- weight prep (both layers) + layer-1 activation prep ----
    prep_w_kernel<<<dim3(4, 4, 8), dim3(32, 8)>>>(Wq1, Wk1, Wv1, Ws1,
                                                  Wq2, Wk2, Wv2, Ws2);
    prep_x_kernel<<<prepBlocks, 256>>>(x);

    // ---- layer 1 ----
    gemm_all_kernel<<<gemmBlocks, 512, smemBytes>>>(0, bq1, bk1, bv1, bs1,
                                                    qp, kp, vp, skp);
    node_attn_kernel<<<nodeBlocks, 256>>>(qp, kp, vp, skp, nullptr, a, xtp, 1);

    // ---- layer 2 ----
    gemm_all_kernel<<<gemmBlocks, 512, smemBytes>>>(4, bq2, bk2, bv2, bs2,
                                                    qp, kp, vp, skp);
    node_attn_kernel<<<nodeBlocks, 256>>>(qp, kp, vp, skp, x, a, out, 0);
}

// round 7
// speedup vs baseline: 3.9612x; 1.1549x over previous
#include <cuda_runtime.h>
#include <cuda_fp16.h>
#include <cstdint>
#include <cstddef>

#define NN 100000
#define EE 1000000
#define DD 128
#define HH 8
#define SCALE_ATT 0.25f   // 1/sqrt(16)
#define LDS_PAD 132       // smem row stride (floats): bank = (4*row + k) % 32
#define NB 98             // scan blocks of 1024 covering NN (+1)

// ---------------- scratch (static device globals) --------------------------
__device__ float   g_xt[NN * DD];      // tf32-rounded activations (GEMM input)
__device__ float   g_wt[8 * DD * DD];  // tf32-rounded, transposed weights Wt[c][k]
__device__ float   g_q[NN * DD];
__device__ __half2 g_kh[NN * DD / 2];  // fp16 k
__device__ __half2 g_vh[NN * DD / 2];  // fp16 v
__device__ float   g_skip[NN * DD];
__device__ int     g_deg[NN];
__device__ int     g_roff[NN + 1];
__device__ int     g_mut[NN];
__device__ int     g_csr[EE];
__device__ int     g_bsum[NB];
__device__ int     g_bpre[NB];

__device__ __forceinline__ float tf32r(float x) {
    uint32_t u;
    asm("cvt.rna.tf32.f32 %0, %1;" : "=r"(u) : "f"(x));
    return __uint_as_float(u);
}

#define CP_ASYNC16(dst_u32, src_ptr) \
    asm volatile("cp.async.cg.shared.global [%0], [%1], 16;" \
                 :: "r"(dst_u32), "l"(src_ptr))
#define CP_ASYNC_COMMIT() asm volatile("cp.async.commit_group;")

// ================= CSR build =================
__global__ void hist_kernel(const int* __restrict__ ei) {
    int e = blockIdx.x * blockDim.x + threadIdx.x;
    if (e < EE) atomicAdd(&g_deg[ei[EE + e]], 1);
}

__global__ void csr_bsum_kernel() {
    __shared__ int sm[1024];
    int tid = threadIdx.x;
    int idx = blockIdx.x * 1024 + tid;
    sm[tid] = (idx < NN) ? g_deg[idx] : 0;
    __syncthreads();
    for (int s = 512; s > 0; s >>= 1) {
        if (tid < s) sm[tid] += sm[tid + s];
        __syncthreads();
    }
    if (tid == 0) g_bsum[blockIdx.x] = sm[0];
}

__global__ void csr_scanb_kernel() {
    __shared__ int sm[128];
    int tid = threadIdx.x;
    int v = (tid < NB) ? g_bsum[tid] : 0;
    sm[tid] = v;
    __syncthreads();
    for (int off = 1; off < 128; off <<= 1) {
        int t = (tid >= off) ? sm[tid - off] : 0;
        __syncthreads();
        sm[tid] += t;
        __syncthreads();
    }
    if (tid < NB) g_bpre[tid] = sm[tid] - v;   // exclusive
}

__global__ void csr_offsets_kernel() {
    __shared__ int sm[1024];
    int tid = threadIdx.x;
    int idx = blockIdx.x * 1024 + tid;
    int v = (idx < NN) ? g_deg[idx] : 0;
    sm[tid] = v;
    __syncthreads();
    for (int off = 1; off < 1024; off <<= 1) {
        int t = (tid >= off) ? sm[tid - off] : 0;
        __syncthreads();
        sm[tid] += t;
        __syncthreads();
    }
    int excl = sm[tid] - v + g_bpre[blockIdx.x];
    if (idx < NN) { g_roff[idx] = excl; g_mut[idx] = excl; }
    if (idx == NN) g_roff[NN] = excl;          // == EE
}

__global__ void csr_scatter_kernel(const int* __restrict__ ei) {
    int e = blockIdx.x * blockDim.x + threadIdx.x;
    if (e >= EE) return;
    int s = ei[e], d = ei[EE + e];
    int pos = atomicAdd(&g_mut[d], 1);
    g_csr[pos] = s;
}

// ================= weight / activation prep =================
__global__ void prep_w_kernel(
    const float* __restrict__ W0, const float* __restrict__ W1,
    const float* __restrict__ W2, const float* __restrict__ W3,
    const float* __restrict__ W4, const float* __restrict__ W5,
    const float* __restrict__ W6, const float* __restrict__ W7)
{
    const float* Ws[8] = {W0, W1, W2, W3, W4, W5, W6, W7};
    int m = blockIdx.z;
    const float* W = Ws[m];
    __shared__ float t[32][33];
    int k0 = blockIdx.x * 32, c0 = blockIdx.y * 32;
    int tx = threadIdx.x, ty = threadIdx.y;
#pragma unroll
    for (int i = 0; i < 4; i++)
        t[ty + 8 * i][tx] = tf32r(W[(k0 + ty + 8 * i) * DD + c0 + tx]);
    __syncthreads();
#pragma unroll
    for (int i = 0; i < 4; i++)
        g_wt[m * DD * DD + (c0 + ty + 8 * i) * DD + k0 + tx] = t[tx][ty + 8 * i];
}

__global__ void prep_x_kernel(const float* __restrict__ X) {
    int i = blockIdx.x * blockDim.x + threadIdx.x;
    if (i >= NN * DD / 4) return;
    float4 v = ((const float4*)X)[i];
    v.x = tf32r(v.x); v.y = tf32r(v.y); v.z = tf32r(v.z); v.w = tf32r(v.w);
    ((float4*)g_xt)[i] = v;
}

// ================= merged 4-matrix tf32 GEMM =================
// One block = one 128-row tile; X loaded once, loops over {q,k,v,skip}
// weights with double-buffered cp.async W prefetch. k and v outputs in fp16.
__global__ __launch_bounds__(512, 1) void gemm_all_kernel(
    int wofs,
    const float* __restrict__ B0, const float* __restrict__ B1,
    const float* __restrict__ B2, const float* __restrict__ B3,
    float* Oq, __half2* Ok, __half2* Ov, float* Osk)
{
    extern __shared__ float smem[];
    float* Xs  = smem;                      // [128][LDS_PAD]
    float* Wb0 = smem + DD * LDS_PAD;       // [128][LDS_PAD]
    float* Wb1 = Wb0 + DD * LDS_PAD;        // [128][LDS_PAD]

    const float* Bs[4] = {B0, B1, B2, B3};

    int row0 = blockIdx.x * 128;
    int tid = threadIdx.x;

    uint32_t xs_b = (uint32_t)__cvta_generic_to_shared(Xs);
    uint32_t w0_b = (uint32_t)__cvta_generic_to_shared(Wb0);
    uint32_t w1_b = (uint32_t)__cvta_generic_to_shared(Wb1);

    const float* Wt0 = g_wt + (size_t)wofs * DD * DD;
#pragma unroll
    for (int it = 0; it < 8; it++) {
        int i = tid + it * 512;
        int r = i >> 5, c4 = (i & 31) * 4;
        int gr = row0 + r; if (gr >= NN) gr = NN - 1;
        CP_ASYNC16(xs_b + (r * LDS_PAD + c4) * 4, g_xt + (size_t)gr * DD + c4);
        CP_ASYNC16(w0_b + (r * LDS_PAD + c4) * 4, Wt0 + (size_t)r * DD + c4);
    }
    CP_ASYNC_COMMIT();

    int warp = tid >> 5, lane = tid & 31;
    int rbase = (warp >> 2) * 32, cbase = (warp & 3) * 32;
    int lr = lane >> 2, lk = lane & 3;

#pragma unroll
    for (int m = 0; m < 4; m++) {
        if (m < 3) {   // prefetch next W into the other buffer
            uint32_t dstb = ((m + 1) & 1) ? w1_b : w0_b;
            const float* Wn = g_wt + (size_t)(wofs + m + 1) * DD * DD;
#pragma unroll
            for (int it = 0; it < 8; it++) {
                int i = tid + it * 512;
                int r = i >> 5, c4 = (i & 31) * 4;
                CP_ASYNC16(dstb + (r * LDS_PAD + c4) * 4, Wn + (size_t)r * DD + c4);
            }
            CP_ASYNC_COMMIT();
            asm volatile("cp.async.wait_group 1;");
        } else {
            asm volatile("cp.async.wait_group 0;");
        }
        __syncthreads();

        const float* Ws = (m & 1) ? Wb1 : Wb0;
        const float* B = Bs[m];

        float acc[2][4][4];
#pragma unroll
        for (int nt = 0; nt < 4; nt++) {
            int col = cbase + nt * 8 + 2 * lk;
            float b0v = B[col], b1v = B[col + 1];
#pragma unroll
            for (int mt = 0; mt < 2; mt++) {
                acc[mt][nt][0] = b0v; acc[mt][nt][1] = b1v;
                acc[mt][nt][2] = b0v; acc[mt][nt][3] = b1v;
            }
        }

#pragma unroll
        for (int ks = 0; ks < 16; ks++) {
            int k0 = ks * 8;
            uint32_t a[2][4];
#pragma unroll
            for (int mt = 0; mt < 2; mt++) {
                const float* base = Xs + (rbase + mt * 16 + lr) * LDS_PAD + k0 + lk;
                a[mt][0] = __float_as_uint(base[0]);
                a[mt][1] = __float_as_uint(base[8 * LDS_PAD]);
                a[mt][2] = __float_as_uint(base[4]);
                a[mt][3] = __float_as_uint(base[8 * LDS_PAD + 4]);
            }
#pragma unroll
            for (int nt = 0; nt < 4; nt++) {
                const float* bbase = Ws + (cbase + nt * 8 + lr) * LDS_PAD + k0 + lk;
                uint32_t b0 = __float_as_uint(bbase[0]);
                uint32_t b1 = __float_as_uint(bbase[4]);
#pragma unroll
                for (int mt = 0; mt < 2; mt++) {
                    asm volatile(
                        "mma.sync.aligned.m16n8k8.row.col.f32.tf32.tf32.f32 "
                        "{%0,%1,%2,%3}, {%4,%5,%6,%7}, {%8,%9}, {%0,%1,%2,%3};"
                        : "+f"(acc[mt][nt][0]), "+f"(acc[mt][nt][1]),
                          "+f"(acc[mt][nt][2]), "+f"(acc[mt][nt][3])
                        : "r"(a[mt][0]), "r"(a[mt][1]), "r"(a[mt][2]), "r"(a[mt][3]),
                          "r"(b0), "r"(b1));
                }
            }
        }

        if (m == 0 || m == 3) {
            float* O = (m == 0) ? Oq : Osk;
#pragma unroll
            for (int mt = 0; mt < 2; mt++) {
                int gr0 = row0 + rbase + mt * 16 + lr;
                int gr1 = gr0 + 8;
#pragma unroll
                for (int nt = 0; nt < 4; nt++) {
                    int col = cbase + nt * 8 + 2 * lk;
                    if (gr0 < NN)
                        *(float2*)(O + (size_t)gr0 * DD + col) =
                            make_float2(acc[mt][nt][0], acc[mt][nt][1]);
                    if (gr1 < NN)
                        *(float2*)(O + (size_t)gr1 * DD + col) =
                            make_float2(acc[mt][nt][2], acc[mt][nt][3]);
                }
            }
        } else {
            __half2* O = (m == 1) ? Ok : Ov;
#pragma unroll
            for (int mt = 0; mt < 2; mt++) {
                int gr0 = row0 + rbase + mt * 16 + lr;
                int gr1 = gr0 + 8;
#pragma unroll
                for (int nt = 0; nt < 4; nt++) {
                    int col = cbase + nt * 8 + 2 * lk;
                    if (gr0 < NN)
                        O[(size_t)gr0 * (DD / 2) + (col >> 1)] =
                            __floats2half2_rn(acc[mt][nt][0], acc[mt][nt][1]);
                    if (gr1 < NN)
                        O[(size_t)gr1 * (DD / 2) + (col >> 1)] =
                            __floats2half2_rn(acc[mt][nt][2], acc[mt][nt][3]);
                }
            }
        }
        __syncthreads();   // protect W buffer before next prefetch overwrites
    }
}

// ================= warp-per-node attention aggregation =================
// Gathers fp16 k/v over the node's in-edges (CSR), softmax (no max shift —
// scores bounded, exp safe), normalize, add skip (+resid), PReLU, write.
__global__ __launch_bounds__(256) void node_attn_kernel(
    const float* __restrict__ q, const __half2* __restrict__ kh,
    const __half2* __restrict__ vh, const float* __restrict__ skip,
    const float* __restrict__ resid, const float* __restrict__ a_ptr,
    float* __restrict__ out, int do_tf32)
{
    int n = (blockIdx.x * blockDim.x + threadIdx.x) >> 5;
    if (n >= NN) return;
    int lane = threadIdx.x & 31;

    float4 qv = ((const float4*)(q + (size_t)n * DD))[lane];
    int j0 = g_roff[n], j1 = g_roff[n + 1];

    float4 acc = make_float4(0.f, 0.f, 0.f, 0.f);
    float ws = 0.f;

#pragma unroll 2
    for (int j = j0; j < j1; j++) {
        int s = g_csr[j];
        // lane covers dims 4l..4l+3: one uint2 = 2 half2
        uint2 kk = ((const uint2*)(kh + (size_t)s * (DD / 2)))[lane];
        float2 k0 = __half22float2(*(const __half2*)&kk.x);
        float2 k1 = __half22float2(*(const __half2*)&kk.y);
        float p = qv.x * k0.x + qv.y * k0.y + qv.z * k1.x + qv.w * k1.y;
        p += __shfl_xor_sync(0xFFFFFFFFu, p, 1);
        p += __shfl_xor_sync(0xFFFFFFFFu, p, 2);
        float w = __expf(p * SCALE_ATT);
        ws += w;
        uint2 vv = ((const uint2*)(vh + (size_t)s * (DD / 2)))[lane];
        float2 v0 = __half22float2(*(const __half2*)&vv.x);
        float2 v1 = __half22float2(*(const __half2*)&vv.y);
        acc.x += w * v0.x; acc.y += w * v0.y;
        acc.z += w * v1.x; acc.w += w * v1.y;
    }

    float inv = (ws > 0.f) ? 1.f / ws : 0.f;
    float4 sk = ((const float4*)(skip + (size_t)n * DD))[lane];
    float4 y;
    y.x = acc.x * inv + sk.x;
    y.y = acc.y * inv + sk.y;
    y.z = acc.z * inv + sk.z;
    y.w = acc.w * inv + sk.w;
    if (resid) {
        float4 rv = ((const float4*)(resid + (size_t)n * DD))[lane];
        y.x += rv.x; y.y += rv.y; y.z += rv.z; y.w += rv.w;
    }
    float a = *a_ptr;
    y.x = (y.x >= 0.f) ? y.x : a * y.x;
    y.y = (y.y >= 0.f) ? y.y : a * y.y;
    y.z = (y.z >= 0.f) ? y.z : a * y.z;
    y.w = (y.w >= 0.f) ? y.w : a * y.w;
    if (do_tf32) {
        y.x = tf32r(y.x); y.y = tf32r(y.y);
        y.z = tf32r(y.z); y.w = tf32r(y.w);
    }
    ((float4*)(out + (size_t)n * DD))[lane] = y;
}

// ---------------- host launch ----------------------------------------------
extern "C" void kernel_launch(void* const* d_in, const int* in_sizes, int n_in,
                              void* d_out, int out_size)
{
    (void)in_sizes; (void)n_in; (void)out_size;
    const float* x   = (const float*)d_in[0];
    const int*   ei  = (const int*)d_in[1];
    const float* a   = (const float*)d_in[2];
    const float* Wq1 = (const float*)d_in[3];  const float* bq1 = (const float*)d_in[4];
    const float* Wk1 = (const float*)d_in[5];  const float* bk1 = (const float*)d_in[6];
    const float* Wv1 = (const float*)d_in[7];  const float* bv1 = (const float*)d_in[8];
    const float* Ws1 = (const float*)d_in[9];  const float* bs1 = (const float*)d_in[10];
    const float* Wq2 = (const float*)d_in[11]; const float* bq2 = (const float*)d_in[12];
    const float* Wk2 = (const float*)d_in[13]; const float* bk2 = (const float*)d_in[14];
    const float* Wv2 = (const float*)d_in[15]; const float* bv2 = (const float*)d_in[16];
    const float* Ws2 = (const float*)d_in[17]; const float* bs2 = (const float*)d_in[18];
    float* out = (float*)d_out;

    float *xtp, *qp, *skp; __half2 *khp, *vhp; int* degp;
    cudaGetSymbolAddress((void**)&xtp, g_xt);
    cudaGetSymbolAddress((void**)&qp,  g_q);
    cudaGetSymbolAddress((void**)&khp, g_kh);
    cudaGetSymbolAddress((void**)&vhp, g_vh);
    cudaGetSymbolAddress((void**)&skp, g_skip);
    cudaGetSymbolAddress((void**)&degp, g_deg);

    const int smemBytes = 3 * DD * LDS_PAD * (int)sizeof(float);  // ~203 KB
    cudaFuncSetAttribute(gemm_all_kernel,
                         cudaFuncAttributeMaxDynamicSharedMemorySize, smemBytes);

    int edgeBlocks = (EE + 255) / 256;
    int nodeBlocks = (NN * 32 + 255) / 256;
    int prepBlocks = (NN * DD / 4 + 255) / 256;
    int gemmBlocks = (NN + 127) / 128;

    // ---- CSR build (graph shared by both layers) ----
    cudaMemsetAsync(degp, 0, NN * sizeof(int));
    hist_kernel<<<edgeBlocks, 256>>>(ei);
    csr_bsum_kernel<<<NB, 1024>>>();
    csr_scanb_kernel<<<1, 128>>>();
    csr_offsets_kernel<<<NB, 1024>>>();
    csr_scatter_kernel<<<edgeBlocks, 256>>>(ei);

    // ---- weight prep (both layers) + layer-1 activation prep ----
    prep_w_kernel<<<dim3(4, 4, 8), dim3(32, 8)>>>(Wq1, Wk1, Wv1, Ws1,
                                                  Wq2, Wk2, Wv2, Ws2);
    prep_x_kernel<<<prepBlocks, 256>>>(x);

    // ---- layer 1 ----
    gemm_all_kernel<<<gemmBlocks, 512, smemBytes>>>(0, bq1, bk1, bv1, bs1,
                                                    qp, khp, vhp, skp);
    node_attn_kernel<<<nodeBlocks, 256>>>(qp, khp, vhp, skp, nullptr, a, xtp, 1);

    // ---- layer 2 ----
    gemm_all_kernel<<<gemmBlocks, 512, smemBytes>>>(4, bq2, bk2, bv2, bs2,
                                                    qp, khp, vhp, skp);
    node_attn_kernel<<<nodeBlocks, 256>>>(qp, khp, vhp, skp, x, a, out, 0);
}

// round 8
// speedup vs baseline: 4.3500x; 1.0982x over previous
#include <cuda_runtime.h>
#include <cuda_fp16.h>
#include <cstdint>
#include <cstddef>

#define NN 100000
#define EE 1000000
#define DD 128
#define HH 8
#define SCALE_ATT 0.25f   // 1/sqrt(16)
#define LDS_PAD 132       // smem row stride (floats)
#define NB 98             // scan blocks of 1024 covering NN (+1)
#define TILE_R 64
#define NTILES ((NN + TILE_R - 1) / TILE_R)   // 1563
#define GEMM_GRID 296

// ---------------- scratch (static device globals) --------------------------
__device__ float   g_xt[NN * DD];      // layer-2 GEMM input (tf32, from attn1)
__device__ float   g_wt[8 * DD * DD];  // tf32-rounded, transposed weights Wt[c][k]
__device__ float   g_q[NN * DD];
__device__ __half2 g_kh[NN * DD / 2];  // fp16 k
__device__ __half2 g_vh[NN * DD / 2];  // fp16 v
__device__ float   g_skip[NN * DD];
__device__ int     g_deg[NN];
__device__ int     g_roff[NN + 1];
__device__ int     g_mut[NN];
__device__ int     g_csr[EE];
__device__ int     g_bsum[NB];
__device__ int     g_bpre[NB];

__device__ __forceinline__ float tf32r(float x) {
    uint32_t u;
    asm("cvt.rna.tf32.f32 %0, %1;" : "=r"(u) : "f"(x));
    return __uint_as_float(u);
}

#define CP_ASYNC16(dst_u32, src_ptr) \
    asm volatile("cp.async.cg.shared.global [%0], [%1], 16;" \
                 :: "r"(dst_u32), "l"(src_ptr))
#define CP_ASYNC_COMMIT() asm volatile("cp.async.commit_group;")
#define CP_ASYNC_WAIT0()  asm volatile("cp.async.wait_group 0;")

// ================= CSR build =================
__global__ void zero_deg_kernel() {
    int i = blockIdx.x * blockDim.x + threadIdx.x;
    if (i < NN) g_deg[i] = 0;
}

__global__ void hist_kernel(const int* __restrict__ ei) {
    int e = blockIdx.x * blockDim.x + threadIdx.x;
    if (e < EE) atomicAdd(&g_deg[ei[EE + e]], 1);
}

__global__ void csr_bsum_kernel() {
    __shared__ int sm[1024];
    int tid = threadIdx.x;
    int idx = blockIdx.x * 1024 + tid;
    sm[tid] = (idx < NN) ? g_deg[idx] : 0;
    __syncthreads();
    for (int s = 512; s > 0; s >>= 1) {
        if (tid < s) sm[tid] += sm[tid + s];
        __syncthreads();
    }
    if (tid == 0) g_bsum[blockIdx.x] = sm[0];
}

__global__ void csr_scanb_kernel() {
    __shared__ int sm[128];
    int tid = threadIdx.x;
    int v = (tid < NB) ? g_bsum[tid] : 0;
    sm[tid] = v;
    __syncthreads();
    for (int off = 1; off < 128; off <<= 1) {
        int t = (tid >= off) ? sm[tid - off] : 0;
        __syncthreads();
        sm[tid] += t;
        __syncthreads();
    }
    if (tid < NB) g_bpre[tid] = sm[tid] - v;   // exclusive
}

__global__ void csr_offsets_kernel() {
    __shared__ int sm[1024];
    int tid = threadIdx.x;
    int idx = blockIdx.x * 1024 + tid;
    int v = (idx < NN) ? g_deg[idx] : 0;
    sm[tid] = v;
    __syncthreads();
    for (int off = 1; off < 1024; off <<= 1) {
        int t = (tid >= off) ? sm[tid - off] : 0;
        __syncthreads();
        sm[tid] += t;
        __syncthreads();
    }
    int excl = sm[tid] - v + g_bpre[blockIdx.x];
    if (idx < NN) { g_roff[idx] = excl; g_mut[idx] = excl; }
    if (idx == NN) g_roff[NN] = excl;          // == EE
}

__global__ void csr_scatter_kernel(const int* __restrict__ ei) {
    int e = blockIdx.x * blockDim.x + threadIdx.x;
    if (e >= EE) return;
    int s = ei[e], d = ei[EE + e];
    int pos = atomicAdd(&g_mut[d], 1);
    g_csr[pos] = s;
}

// ================= weight prep =================
__global__ void prep_w_kernel(
    const float* __restrict__ W0, const float* __restrict__ W1,
    const float* __restrict__ W2, const float* __restrict__ W3,
    const float* __restrict__ W4, const float* __restrict__ W5,
    const float* __restrict__ W6, const float* __restrict__ W7)
{
    const float* Ws[8] = {W0, W1, W2, W3, W4, W5, W6, W7};
    int m = blockIdx.z;
    const float* W = Ws[m];
    __shared__ float t[32][33];
    int k0 = blockIdx.x * 32, c0 = blockIdx.y * 32;
    int tx = threadIdx.x, ty = threadIdx.y;
#pragma unroll
    for (int i = 0; i < 4; i++)
        t[ty + 8 * i][tx] = tf32r(W[(k0 + ty + 8 * i) * DD + c0 + tx]);
    __syncthreads();
#pragma unroll
    for (int i = 0; i < 4; i++)
        g_wt[m * DD * DD + (c0 + ty + 8 * i) * DD + k0 + tx] = t[tx][ty + 8 * i];
}

// ================= persistent merged 4-matrix tf32 GEMM =================
// 296 blocks (2 CTA/SM), 256 threads. m (weight matrix) outer loop: W loaded
// once per m per block; 64-row X tiles inner, rounded to tf32 in-register.
__global__ __launch_bounds__(256, 2) void gemm_all_kernel(
    int wofs, const float* __restrict__ X,
    const float* __restrict__ B0, const float* __restrict__ B1,
    const float* __restrict__ B2, const float* __restrict__ B3,
    float* Oq, __half2* Ok, __half2* Ov, float* Osk)
{
    extern __shared__ float smem[];
    float* Xs = smem;                       // [64][LDS_PAD]
    float* Ws = smem + TILE_R * LDS_PAD;    // [128][LDS_PAD]  W[c][k]

    const float* Bs[4] = {B0, B1, B2, B3};

    int tid = threadIdx.x;
    int warp = tid >> 5, lane = tid & 31;
    int rbase = (warp >> 2) * 32;           // {0,32}
    int cbase = (warp & 3) * 32;            // {0,32,64,96}
    int lr = lane >> 2, lk = lane & 3;

    uint32_t ws_b = (uint32_t)__cvta_generic_to_shared(Ws);

#pragma unroll 1
    for (int m = 0; m < 4; m++) {
        // load W_m (128 c-rows x 128 k) via cp.async
        const float* Wt = g_wt + (size_t)(wofs + m) * DD * DD;
#pragma unroll
        for (int it = 0; it < 16; it++) {
            int i = tid + it * 256;
            int r = i >> 5, c4 = (i & 31) * 4;
            CP_ASYNC16(ws_b + (r * LDS_PAD + c4) * 4, Wt + (size_t)r * DD + c4);
        }
        CP_ASYNC_COMMIT();

        const float* B = Bs[m];
        float bb[4][2];
#pragma unroll
        for (int nt = 0; nt < 4; nt++) {
            int col = cbase + nt * 8 + 2 * lk;
            bb[nt][0] = B[col]; bb[nt][1] = B[col + 1];
        }

        CP_ASYNC_WAIT0();

        for (int t = blockIdx.x; t < NTILES; t += GEMM_GRID) {
            int row0 = t * TILE_R;
            __syncthreads();   // prior compute done (Xs safe) + W visible
            // load X tile, tf32-round in-register
#pragma unroll
            for (int it = 0; it < 8; it++) {
                int i = tid + it * 256;
                int r = i >> 5, c4 = (i & 31) * 4;
                int gr = row0 + r; if (gr >= NN) gr = NN - 1;
                float4 xv = *(const float4*)(X + (size_t)gr * DD + c4);
                float* p = Xs + r * LDS_PAD + c4;
                p[0] = tf32r(xv.x); p[1] = tf32r(xv.y);
                p[2] = tf32r(xv.z); p[3] = tf32r(xv.w);
            }
            __syncthreads();

            float acc[2][4][4];
#pragma unroll
            for (int nt = 0; nt < 4; nt++)
#pragma unroll
                for (int mt = 0; mt < 2; mt++) {
                    acc[mt][nt][0] = bb[nt][0]; acc[mt][nt][1] = bb[nt][1];
                    acc[mt][nt][2] = bb[nt][0]; acc[mt][nt][3] = bb[nt][1];
                }

#pragma unroll
            for (int ks = 0; ks < 16; ks++) {
                int k0 = ks * 8;
                uint32_t a[2][4];
#pragma unroll
                for (int mt = 0; mt < 2; mt++) {
                    const float* base = Xs + (rbase + mt * 16 + lr) * LDS_PAD + k0 + lk;
                    a[mt][0] = __float_as_uint(base[0]);
                    a[mt][1] = __float_as_uint(base[8 * LDS_PAD]);
                    a[mt][2] = __float_as_uint(base[4]);
                    a[mt][3] = __float_as_uint(base[8 * LDS_PAD + 4]);
                }
#pragma unroll
                for (int nt = 0; nt < 4; nt++) {
                    const float* bbase = Ws + (cbase + nt * 8 + lr) * LDS_PAD + k0 + lk;
                    uint32_t b0 = __float_as_uint(bbase[0]);
                    uint32_t b1 = __float_as_uint(bbase[4]);
#pragma unroll
                    for (int mt = 0; mt < 2; mt++) {
                        asm volatile(
                            "mma.sync.aligned.m16n8k8.row.col.f32.tf32.tf32.f32 "
                            "{%0,%1,%2,%3}, {%4,%5,%6,%7}, {%8,%9}, {%0,%1,%2,%3};"
                            : "+f"(acc[mt][nt][0]), "+f"(acc[mt][nt][1]),
                              "+f"(acc[mt][nt][2]), "+f"(acc[mt][nt][3])
                            : "r"(a[mt][0]), "r"(a[mt][1]), "r"(a[mt][2]), "r"(a[mt][3]),
                              "r"(b0), "r"(b1));
                    }
                }
            }

            if (m == 0 || m == 3) {
                float* O = (m == 0) ? Oq : Osk;
#pragma unroll
                for (int mt = 0; mt < 2; mt++) {
                    int gr0 = row0 + rbase + mt * 16 + lr;
                    int gr1 = gr0 + 8;
#pragma unroll
                    for (int nt = 0; nt < 4; nt++) {
                        int col = cbase + nt * 8 + 2 * lk;
                        if (gr0 < NN)
                            *(float2*)(O + (size_t)gr0 * DD + col) =
                                make_float2(acc[mt][nt][0], acc[mt][nt][1]);
                        if (gr1 < NN)
                            *(float2*)(O + (size_t)gr1 * DD + col) =
                                make_float2(acc[mt][nt][2], acc[mt][nt][3]);
                    }
                }
            } else {
                __half2* O = (m == 1) ? Ok : Ov;
#pragma unroll
                for (int mt = 0; mt < 2; mt++) {
                    int gr0 = row0 + rbase + mt * 16 + lr;
                    int gr1 = gr0 + 8;
#pragma unroll
                    for (int nt = 0; nt < 4; nt++) {
                        int col = cbase + nt * 8 + 2 * lk;
                        if (gr0 < NN)
                            O[(size_t)gr0 * (DD / 2) + (col >> 1)] =
                                __floats2half2_rn(acc[mt][nt][0], acc[mt][nt][1]);
                        if (gr1 < NN)
                            O[(size_t)gr1 * (DD / 2) + (col >> 1)] =
                                __floats2half2_rn(acc[mt][nt][2], acc[mt][nt][3]);
                    }
                }
            }
        }
        __syncthreads();   // all reads of Ws done before next m overwrites
    }
}

// ================= warp-per-node attention aggregation =================
__global__ __launch_bounds__(256) void node_attn_kernel(
    const float* __restrict__ q, const __half2* __restrict__ kh,
    const __half2* __restrict__ vh, const float* __restrict__ skip,
    const float* __restrict__ resid, const float* __restrict__ a_ptr,
    float* __restrict__ out, int do_tf32)
{
    int n = (blockIdx.x * blockDim.x + threadIdx.x) >> 5;
    if (n >= NN) return;
    int lane = threadIdx.x & 31;

    float4 qv = ((const float4*)(q + (size_t)n * DD))[lane];
    int j0 = g_roff[n], j1 = g_roff[n + 1];

    float4 acc = make_float4(0.f, 0.f, 0.f, 0.f);
    float ws = 0.f;

#pragma unroll 4
    for (int j = j0; j < j1; j++) {
        int s = g_csr[j];
        uint2 kk = ((const uint2*)(kh + (size_t)s * (DD / 2)))[lane];
        float2 k0 = __half22float2(*(const __half2*)&kk.x);
        float2 k1 = __half22float2(*(const __half2*)&kk.y);
        float p = qv.x * k0.x + qv.y * k0.y + qv.z * k1.x + qv.w * k1.y;
        p += __shfl_xor_sync(0xFFFFFFFFu, p, 1);
        p += __shfl_xor_sync(0xFFFFFFFFu, p, 2);
        float w = __expf(p * SCALE_ATT);
        ws += w;
        uint2 vv = ((const uint2*)(vh + (size_t)s * (DD / 2)))[lane];
        float2 v0 = __half22float2(*(const __half2*)&vv.x);
        float2 v1 = __half22float2(*(const __half2*)&vv.y);
        acc.x += w * v0.x; acc.y += w * v0.y;
        acc.z += w * v1.x; acc.w += w * v1.y;
    }

    float inv = (ws > 0.f) ? 1.f / ws : 0.f;
    float4 sk = ((const float4*)(skip + (size_t)n * DD))[lane];
    float4 y;
    y.x = acc.x * inv + sk.x;
    y.y = acc.y * inv + sk.y;
    y.z = acc.z * inv + sk.z;
    y.w = acc.w * inv + sk.w;
    if (resid) {
        float4 rv = ((const float4*)(resid + (size_t)n * DD))[lane];
        y.x += rv.x; y.y += rv.y; y.z += rv.z; y.w += rv.w;
    }
    float a = *a_ptr;
    y.x = (y.x >= 0.f) ? y.x : a * y.x;
    y.y = (y.y >= 0.f) ? y.y : a * y.y;
    y.z = (y.z >= 0.f) ? y.z : a * y.z;
    y.w = (y.w >= 0.f) ? y.w : a * y.w;
    if (do_tf32) {
        y.x = tf32r(y.x); y.y = tf32r(y.y);
        y.z = tf32r(y.z); y.w = tf32r(y.w);
    }
    ((float4*)(out + (size_t)n * DD))[lane] = y;
}

// ---------------- host launch ----------------------------------------------
extern "C" void kernel_launch(void* const* d_in, const int* in_sizes, int n_in,
                              void* d_out, int out_size)
{
    (void)in_sizes; (void)n_in; (void)out_size;
    const float* x   = (const float*)d_in[0];
    const int*   ei  = (const int*)d_in[1];
    const float* a   = (const float*)d_in[2];
    const float* Wq1 = (const float*)d_in[3];  const float* bq1 = (const float*)d_in[4];
    const float* Wk1 = (const float*)d_in[5];  const float* bk1 = (const float*)d_in[6];
    const float* Wv1 = (const float*)d_in[7];  const float* bv1 = (const float*)d_in[8];
    const float* Ws1 = (const float*)d_in[9];  const float* bs1 = (const float*)d_in[10];
    const float* Wq2 = (const float*)d_in[11]; const float* bq2 = (const float*)d_in[12];
    const float* Wk2 = (const float*)d_in[13]; const float* bk2 = (const float*)d_in[14];
    const float* Wv2 = (const float*)d_in[15]; const float* bv2 = (const float*)d_in[16];
    const float* Ws2 = (const float*)d_in[17]; const float* bs2 = (const float*)d_in[18];
    float* out = (float*)d_out;

    float *xtp, *qp, *skp; __half2 *khp, *vhp;
    cudaGetSymbolAddress((void**)&xtp, g_xt);
    cudaGetSymbolAddress((void**)&qp,  g_q);
    cudaGetSymbolAddress((void**)&khp, g_kh);
    cudaGetSymbolAddress((void**)&vhp, g_vh);
    cudaGetSymbolAddress((void**)&skp, g_skip);

    const int smemBytes = (TILE_R + DD) * LDS_PAD * (int)sizeof(float);  // ~99 KB
    cudaFuncSetAttribute(gemm_all_kernel,
                         cudaFuncAttributeMaxDynamicSharedMemorySize, smemBytes);

    int edgeBlocks = (EE + 255) / 256;
    int nodeBlocks = (NN * 32 + 255) / 256;
    int zeroBlocks = (NN + 1023) / 1024;

    // Launch order chosen so gemm1 is the 6th kernel (ncu -s 5 -c 1 profiles it),
    // while respecting deps: offsets needs scanb; scatter needs offsets;
    // attn1 needs scatter + gemm1.
    zero_deg_kernel<<<zeroBlocks, 1024>>>();                              // 1
    prep_w_kernel<<<dim3(4, 4, 8), dim3(32, 8)>>>(Wq1, Wk1, Wv1, Ws1,
                                                  Wq2, Wk2, Wv2, Ws2);    // 2
    hist_kernel<<<edgeBlocks, 256>>>(ei);                                 // 3
    csr_bsum_kernel<<<NB, 1024>>>();                                      // 4
    csr_scanb_kernel<<<1, 128>>>();                                       // 5
    gemm_all_kernel<<<GEMM_GRID, 256, smemBytes>>>(0, x,
        bq1, bk1, bv1, bs1, qp, khp, vhp, skp);                           // 6 <- profiled
    csr_offsets_kernel<<<NB, 1024>>>();                                   // 7
    csr_scatter_kernel<<<edgeBlocks, 256>>>(ei);                          // 8
    node_attn_kernel<<<nodeBlocks, 256>>>(qp, khp, vhp, skp,
                                          nullptr, a, xtp, 1);            // 9
    gemm_all_kernel<<<GEMM_GRID, 256, smemBytes>>>(4, xtp,
        bq2, bk2, bv2, bs2, qp, khp, vhp, skp);                           // 10
    node_attn_kernel<<<nodeBlocks, 256>>>(qp, khp, vhp, skp,
                                          x, a, out, 0);                  // 11
}